// round 4
// baseline (speedup 1.0000x reference)
#include <cuda_runtime.h>
#include <cstdint>

// ---------------- problem constants (fixed by dataset) ----------------
#define NMAX 100000
#define D    64
#define H    128
#define DV   (D / 4)   // 16 float4 per row

// ---------------- device scratch (static allocation, allowed) ---------
__device__ float4 g_xn4 [ (size_t)NMAX * DV ];   // normalized features
__device__ float4 g_agg4[ (size_t)NMAX * DV ];   // segment sums
__device__ float  g_deg [ NMAX ];                // degree
__device__ float  g_stats[ 2 * D ];              // colsum / colsumsq

// ---------------- kernel 0: zero scratch ------------------------------
__global__ void k_zero(int N) {
    int i = blockIdx.x * blockDim.x + threadIdx.x;
    int stride = gridDim.x * blockDim.x;
    int n4 = N * DV;
    float4 z = make_float4(0.f, 0.f, 0.f, 0.f);
    for (int k = i; k < n4; k += stride) g_agg4[k] = z;
    for (int k = i; k < N; k += stride) g_deg[k] = 0.f;
    if (i < 2 * D) g_stats[i] = 0.f;
}

// ---------------- kernel 1: BN column statistics ----------------------
__global__ void k_stats(const float* __restrict__ x, int N) {
    __shared__ float s_sum[4][D];
    __shared__ float s_sq [4][D];
    int c  = threadIdx.x & (D - 1);
    int rg = threadIdx.x >> 6;
    int row0 = blockIdx.x * 1024;
    int rend = min(row0 + 1024, N);
    float s = 0.f, q = 0.f;
    for (int r = row0 + rg; r < rend; r += 4) {
        float v = x[(size_t)r * D + c];
        s += v; q += v * v;
    }
    s_sum[rg][c] = s; s_sq[rg][c] = q;
    __syncthreads();
    if (threadIdx.x < D) {
        float S = s_sum[0][c] + s_sum[1][c] + s_sum[2][c] + s_sum[3][c];
        float Q = s_sq [0][c] + s_sq [1][c] + s_sq [2][c] + s_sq [3][c];
        atomicAdd(&g_stats[c], S);
        atomicAdd(&g_stats[D + c], Q);
    }
}

// ---------------- kernel 2: normalize (vectorized) --------------------
__global__ void k_norm(const float* __restrict__ x,
                       const float* __restrict__ gamma,
                       const float* __restrict__ beta, int N) {
    __shared__ float sc[D], sb[D];
    if (threadIdx.x < D) {
        int c = threadIdx.x;
        float invN = 1.0f / (float)N;
        float mean = g_stats[c] * invN;
        float var  = g_stats[D + c] * invN - mean * mean;
        float inv  = rsqrtf(var + 1e-5f);
        float g    = gamma[c];
        sc[c] = inv * g;
        sb[c] = beta[c] - mean * inv * g;
    }
    __syncthreads();
    const float4* x4 = reinterpret_cast<const float4*>(x);
    int total = N * DV;
    int stride = gridDim.x * blockDim.x;
    for (int i = blockIdx.x * blockDim.x + threadIdx.x; i < total; i += stride) {
        int c = (i & (DV - 1)) * 4;
        float4 v = x4[i];
        v.x = v.x * sc[c + 0] + sb[c + 0];
        v.y = v.y * sc[c + 1] + sb[c + 1];
        v.z = v.z * sc[c + 2] + sb[c + 2];
        v.w = v.w * sc[c + 3] + sb[c + 3];
        g_xn4[i] = v;
    }
}

// ---------------- kernel 3: edge scatter (int32 indices, guarded) -----
// 16 threads per edge, one float4 vector reduction-atomic per thread.
__global__ void k_scatter(const int* __restrict__ ei, int E, int N) {
    long long idx = (long long)blockIdx.x * blockDim.x + threadIdx.x;
    int e = (int)(idx >> 4);
    if (e >= E) return;
    int lane = (int)(idx & 15);
    int src = ei[e];
    int dst = ei[(size_t)E + e];
    // bounds guard: crash-proof against dtype/layout surprises
    if ((unsigned)src >= (unsigned)N || (unsigned)dst >= (unsigned)N) return;
    float4 v = g_xn4[(size_t)src * DV + lane];
#if __CUDA_ARCH__ >= 900
    atomicAdd(&g_agg4[(size_t)dst * DV + lane], v);
#else
    float* p = reinterpret_cast<float*>(&g_agg4[(size_t)dst * DV + lane]);
    atomicAdd(p + 0, v.x); atomicAdd(p + 1, v.y);
    atomicAdd(p + 2, v.z); atomicAdd(p + 3, v.w);
#endif
    if (lane == 0) atomicAdd(&g_deg[dst], 1.0f);
}

// ---------------- kernel 4: fused node GEMM + classifier --------------
// h = relu([agg/deg, xn] @ [W_l; W_r] + b_l)
// out = relu(h @ W1 + b1) @ W2 + b2
#define BM 64
#define BK 16
__global__ void __launch_bounds__(256, 4)
k_fused(const float* __restrict__ Wl, const float* __restrict__ bl,
        const float* __restrict__ Wr, const float* __restrict__ W1,
        const float* __restrict__ b1, const float* __restrict__ W2,
        const float* __restrict__ b2, float* __restrict__ out, int N) {
    __shared__ float u_s[BK][BM];        // concat-feature tile (transposed)
    __shared__ float W_s[BK][H];         // weight tile
    __shared__ float h_s[BM][H + 4];     // hidden tile, padded
    __shared__ float W1T[16][H];         // W1 transposed
    __shared__ float bl_s[H];

    int t  = threadIdx.x;
    int m0 = blockIdx.x * BM;
    int c  = t & 31;     // h-column group: cols c*4..c*4+3
    int r  = t >> 5;     // node-row group (warp-uniform): rows r*8..r*8+7

    if (t < H) bl_s[t] = bl[t];
    for (int i = t; i < H * 16; i += 256) {  // W1 [128][16] -> W1T[j][h]
        int hh = i >> 4, j = i & 15;
        W1T[j][hh] = W1[i];
    }

    float acc[8][4];
    #pragma unroll
    for (int i = 0; i < 8; i++)
        #pragma unroll
        for (int j = 0; j < 4; j++) acc[i][j] = 0.f;

    #pragma unroll
    for (int kb = 0; kb < (2 * D) / BK; kb++) {
        __syncthreads();
        // load u tile: 16 k x 64 m, transposed store
        {
            int mi = t & 63, k4 = t >> 6;       // k4 in 0..3, 4 floats each
            int kg = kb * BK + k4 * 4;
            int node = m0 + mi;
            float4 v = make_float4(0.f, 0.f, 0.f, 0.f);
            if (node < N) {
                if (kg < D) {
                    v = g_agg4[(size_t)node * DV + (kg >> 2)];
                    float inv = 1.0f / fmaxf(g_deg[node], 1.0f);
                    v.x *= inv; v.y *= inv; v.z *= inv; v.w *= inv;
                } else {
                    v = g_xn4[(size_t)node * DV + ((kg - D) >> 2)];
                }
            }
            u_s[k4 * 4 + 0][mi] = v.x;
            u_s[k4 * 4 + 1][mi] = v.y;
            u_s[k4 * 4 + 2][mi] = v.z;
            u_s[k4 * 4 + 3][mi] = v.w;
        }
        // load W tile: 16 k x 128 h
        for (int i = t; i < BK * 32; i += 256) {
            int h4 = i & 31, k = i >> 5;
            int kg = kb * BK + k;
            const float* Wsrc = (kg < D) ? (Wl + (size_t)kg * H)
                                         : (Wr + (size_t)(kg - D) * H);
            *reinterpret_cast<float4*>(&W_s[k][h4 * 4]) =
                *reinterpret_cast<const float4*>(Wsrc + h4 * 4);
        }
        __syncthreads();
        #pragma unroll
        for (int k = 0; k < BK; k++) {
            float a[8], b[4];
            *reinterpret_cast<float4*>(a)     = *reinterpret_cast<float4*>(&u_s[k][r * 8]);
            *reinterpret_cast<float4*>(a + 4) = *reinterpret_cast<float4*>(&u_s[k][r * 8 + 4]);
            *reinterpret_cast<float4*>(b)     = *reinterpret_cast<float4*>(&W_s[k][c * 4]);
            #pragma unroll
            for (int i = 0; i < 8; i++)
                #pragma unroll
                for (int j = 0; j < 4; j++)
                    acc[i][j] += a[i] * b[j];
        }
    }
    __syncthreads();
    // bias + relu -> h_s
    #pragma unroll
    for (int i = 0; i < 8; i++)
        #pragma unroll
        for (int j = 0; j < 4; j++)
            h_s[r * 8 + i][c * 4 + j] = fmaxf(acc[i][j] + bl_s[c * 4 + j], 0.f);
    __syncthreads();

    // -------- classifier: 4 threads per node --------
    int n = t >> 2;      // local node 0..63
    int q = t & 3;       // handles t-cols q*4..q*4+3
    float tt[4];
    #pragma unroll
    for (int j = 0; j < 4; j++) tt[j] = b1[q * 4 + j];
    #pragma unroll
    for (int h4 = 0; h4 < H / 4; h4++) {
        float4 hv = *reinterpret_cast<float4*>(&h_s[n][h4 * 4]);
        #pragma unroll
        for (int j = 0; j < 4; j++) {
            float4 wv = *reinterpret_cast<float4*>(&W1T[q * 4 + j][h4 * 4]);
            tt[j] += hv.x * wv.x + hv.y * wv.y + hv.z * wv.z + hv.w * wv.w;
        }
    }
    float o0 = 0.f, o1 = 0.f;
    #pragma unroll
    for (int j = 0; j < 4; j++) {
        float tv = fmaxf(tt[j], 0.f);
        o0 += tv * W2[(q * 4 + j) * 2 + 0];
        o1 += tv * W2[(q * 4 + j) * 2 + 1];
    }
    o0 += __shfl_xor_sync(0xffffffffu, o0, 1);
    o0 += __shfl_xor_sync(0xffffffffu, o0, 2);
    o1 += __shfl_xor_sync(0xffffffffu, o1, 1);
    o1 += __shfl_xor_sync(0xffffffffu, o1, 2);
    int node = m0 + n;
    if (q == 0 && node < N) {
        out[(size_t)node * 2 + 0] = o0 + b2[0];
        out[(size_t)node * 2 + 1] = o1 + b2[1];
    }
}

// ---------------- launcher --------------------------------------------
extern "C" void kernel_launch(void* const* d_in, const int* in_sizes, int n_in,
                              void* d_out, int out_size) {
    const float* x  = (const float*)d_in[0];
    const int*   ei = (const int*)d_in[1];     // int64 in reference -> int32 in harness
    int N = in_sizes[0] / D;
    int E = in_sizes[1] / 2;

    // Locate weights by exact size sequence (robust to scalar inputs
    // being present or absent): gamma,beta,W_l,b_l,W_r,W1,b1,W2,b2
    const int want[9] = {64, 64, 8192, 128, 8192, 2048, 16, 32, 2};
    const float* w[9] = {nullptr, nullptr, nullptr, nullptr, nullptr,
                         nullptr, nullptr, nullptr, nullptr};
    int j = 0;
    for (int i = 2; i < n_in && j < 9; i++) {
        if (in_sizes[i] == want[j]) { w[j] = (const float*)d_in[i]; j++; }
    }
    const float *gamma = w[0], *beta = w[1], *Wl = w[2], *bl = w[3],
                *Wr = w[4], *W1 = w[5], *b1 = w[6], *W2 = w[7], *b2 = w[8];
    float* out = (float*)d_out;

    k_zero<<<1024, 256>>>(N);
    k_stats<<<(N + 1023) / 1024, 256>>>(x, N);
    k_norm<<<2048, 256>>>(x, gamma, beta, N);
    long long total = (long long)E * 16;
    k_scatter<<<(int)((total + 255) / 256), 256>>>(ei, E, N);
    k_fused<<<(N + BM - 1) / BM, 256>>>(Wl, bl, Wr, W1, b1, W2, b2, out, N);
}

// round 5
// speedup vs baseline: 1.5052x; 1.5052x over previous
#include <cuda_runtime.h>
#include <cstdint>

// ---------------- problem constants (fixed by dataset) ----------------
#define NMAX 100000
#define D    64
#define H    128
#define DV   (D / 4)   // 16 float4 per row

// ---------------- device scratch (static allocation, allowed) ---------
__device__ float4 g_xn4 [ (size_t)NMAX * DV ];   // normalized features
__device__ float4 g_agg4[ (size_t)NMAX * DV ];   // segment sums
__device__ float  g_deg [ NMAX ];                // degree
__device__ float  g_stats[ 2 * D ];              // colsum / colsumsq

// ---------------- helpers ---------------------------------------------
__device__ __forceinline__ float f2tf32f(float x) {
    uint32_t r;
    asm("cvt.rna.tf32.f32 %0, %1;" : "=r"(r) : "f"(x));
    return __uint_as_float(r);
}

__device__ __forceinline__ void mma_tf32(float* c, const uint32_t* a,
                                         uint32_t b0, uint32_t b1) {
    asm("mma.sync.aligned.m16n8k8.row.col.f32.tf32.tf32.f32 "
        "{%0,%1,%2,%3}, {%4,%5,%6,%7}, {%8,%9}, {%0,%1,%2,%3};"
        : "+f"(c[0]), "+f"(c[1]), "+f"(c[2]), "+f"(c[3])
        : "r"(a[0]), "r"(a[1]), "r"(a[2]), "r"(a[3]), "r"(b0), "r"(b1));
}

// ---------------- kernel 0: zero scratch ------------------------------
__global__ void k_zero(int N) {
    int i = blockIdx.x * blockDim.x + threadIdx.x;
    int stride = gridDim.x * blockDim.x;
    int n4 = N * DV;
    float4 z = make_float4(0.f, 0.f, 0.f, 0.f);
    for (int k = i; k < n4; k += stride) g_agg4[k] = z;
    for (int k = i; k < N; k += stride) g_deg[k] = 0.f;
    if (i < 2 * D) g_stats[i] = 0.f;
}

// ---------------- kernel 1: BN column statistics ----------------------
__global__ void k_stats(const float* __restrict__ x, int N) {
    __shared__ float s_sum[4][D];
    __shared__ float s_sq [4][D];
    int c  = threadIdx.x & (D - 1);
    int rg = threadIdx.x >> 6;
    int row0 = blockIdx.x * 1024;
    int rend = min(row0 + 1024, N);
    float s = 0.f, q = 0.f;
    for (int r = row0 + rg; r < rend; r += 4) {
        float v = x[(size_t)r * D + c];
        s += v; q += v * v;
    }
    s_sum[rg][c] = s; s_sq[rg][c] = q;
    __syncthreads();
    if (threadIdx.x < D) {
        float S = s_sum[0][c] + s_sum[1][c] + s_sum[2][c] + s_sum[3][c];
        float Q = s_sq [0][c] + s_sq [1][c] + s_sq [2][c] + s_sq [3][c];
        atomicAdd(&g_stats[c], S);
        atomicAdd(&g_stats[D + c], Q);
    }
}

// ---------------- kernel 2: normalize (vectorized) --------------------
__global__ void k_norm(const float* __restrict__ x,
                       const float* __restrict__ gamma,
                       const float* __restrict__ beta, int N) {
    __shared__ float sc[D], sb[D];
    if (threadIdx.x < D) {
        int c = threadIdx.x;
        float invN = 1.0f / (float)N;
        float mean = g_stats[c] * invN;
        float var  = g_stats[D + c] * invN - mean * mean;
        float inv  = rsqrtf(var + 1e-5f);
        float g    = gamma[c];
        sc[c] = inv * g;
        sb[c] = beta[c] - mean * inv * g;
    }
    __syncthreads();
    const float4* x4 = reinterpret_cast<const float4*>(x);
    int total = N * DV;
    int stride = gridDim.x * blockDim.x;
    for (int i = blockIdx.x * blockDim.x + threadIdx.x; i < total; i += stride) {
        int c = (i & (DV - 1)) * 4;
        float4 v = x4[i];
        v.x = v.x * sc[c + 0] + sb[c + 0];
        v.y = v.y * sc[c + 1] + sb[c + 1];
        v.z = v.z * sc[c + 2] + sb[c + 2];
        v.w = v.w * sc[c + 3] + sb[c + 3];
        g_xn4[i] = v;
    }
}

// ---------------- kernel 3: edge scatter (int32 indices, guarded) -----
__global__ void k_scatter(const int* __restrict__ ei, int E, int N) {
    long long idx = (long long)blockIdx.x * blockDim.x + threadIdx.x;
    int e = (int)(idx >> 4);
    if (e >= E) return;
    int lane = (int)(idx & 15);
    int src = ei[e];
    int dst = ei[(size_t)E + e];
    if ((unsigned)src >= (unsigned)N || (unsigned)dst >= (unsigned)N) return;
    float4 v = g_xn4[(size_t)src * DV + lane];
    atomicAdd(&g_agg4[(size_t)dst * DV + lane], v);
    if (lane == 0) atomicAdd(&g_deg[dst], 1.0f);
}

// ---------------- kernel 4: tf32 tensor-core GEMM + fused classifier --
// h = relu([agg/deg, xn] @ [W_l; W_r] + b_l)     (tf32 mma, fp32 accum)
// out = relu(h @ W1 + b1) @ W2 + b2              (fp32, from mma fragments)
// Block: 256 thr = 8 warps. Tile: 128 nodes x 128 h. K=128 in 4 chunks of 32.
#define U_STRIDE 36
#define W_STRIDE 132
__global__ void __launch_bounds__(256)
k_fused_tc(const float* __restrict__ Wl, const float* __restrict__ bl,
           const float* __restrict__ Wr, const float* __restrict__ W1,
           const float* __restrict__ b1, const float* __restrict__ W2,
           const float* __restrict__ b2, float* __restrict__ out, int N) {
    __shared__ float s_u [128 * U_STRIDE];   // U chunk  [128 rows][32 k], tf32
    __shared__ float s_w [32 * W_STRIDE];    // W chunk  [32 k][128 h], tf32
    __shared__ float s_w1t[16 * 128];        // W1^T [j][h]
    __shared__ float s_bl[128];

    int t    = threadIdx.x;
    int w    = t >> 5;
    int lane = t & 31;
    int g    = lane >> 2;     // group id 0..7
    int tq   = lane & 3;      // thread-in-quad 0..3
    int m0   = blockIdx.x * 128;

    if (t < 128) s_bl[t] = bl[t];
    for (int i = t; i < 16 * 128; i += 256) {      // W1 [128][16] -> W1T[j][h]
        int c = i & 127, j = i >> 7;
        s_w1t[j * 128 + c] = W1[c * 16 + j];
    }

    float acc[16][4];
    #pragma unroll
    for (int n = 0; n < 16; n++)
        #pragma unroll
        for (int j = 0; j < 4; j++) acc[n][j] = 0.f;

    #pragma unroll
    for (int kb = 0; kb < 4; kb++) {
        __syncthreads();
        // ---- load U chunk: 128 rows x 32 k (tf32) ----
        #pragma unroll
        for (int ii = 0; ii < 4; ii++) {
            int i = t + 256 * ii;            // 0..1023 float4 units
            int row = i >> 3, k4 = i & 7;
            int node = m0 + row;
            int kg = kb * 32 + k4 * 4;
            float4 v = make_float4(0.f, 0.f, 0.f, 0.f);
            if (node < N) {
                if (kg < D) {
                    v = g_agg4[(size_t)node * DV + (kg >> 2)];
                    float inv = 1.0f / fmaxf(g_deg[node], 1.0f);
                    v.x *= inv; v.y *= inv; v.z *= inv; v.w *= inv;
                } else {
                    v = g_xn4[(size_t)node * DV + ((kg - D) >> 2)];
                }
            }
            float* p = &s_u[row * U_STRIDE + k4 * 4];
            p[0] = f2tf32f(v.x); p[1] = f2tf32f(v.y);
            p[2] = f2tf32f(v.z); p[3] = f2tf32f(v.w);
        }
        // ---- load W chunk: 32 k x 128 h (tf32) ----
        #pragma unroll
        for (int ii = 0; ii < 4; ii++) {
            int i = t + 256 * ii;            // 0..1023 float4 units
            int k = i >> 5, h4 = i & 31;
            int kg = kb * 32 + k;
            const float* src = (kg < D) ? (Wl + (size_t)kg * H + h4 * 4)
                                        : (Wr + (size_t)(kg - D) * H + h4 * 4);
            float4 v = *reinterpret_cast<const float4*>(src);
            float* p = &s_w[k * W_STRIDE + h4 * 4];
            p[0] = f2tf32f(v.x); p[1] = f2tf32f(v.y);
            p[2] = f2tf32f(v.z); p[3] = f2tf32f(v.w);
        }
        __syncthreads();

        // ---- A fragments for this chunk (4 k-steps of 8) ----
        uint32_t A[4][4];
        int arow = (w * 16 + g) * U_STRIDE;
        #pragma unroll
        for (int kk = 0; kk < 4; kk++) {
            int kof = kk * 8 + tq;
            A[kk][0] = __float_as_uint(s_u[arow + kof]);
            A[kk][1] = __float_as_uint(s_u[arow + 8 * U_STRIDE + kof]);
            A[kk][2] = __float_as_uint(s_u[arow + kof + 4]);
            A[kk][3] = __float_as_uint(s_u[arow + 8 * U_STRIDE + kof + 4]);
        }
        // ---- 16 n-tiles x 4 k-steps of mma ----
        #pragma unroll
        for (int nt = 0; nt < 16; nt++) {
            int bcol = nt * 8 + g;
            #pragma unroll
            for (int kk = 0; kk < 4; kk++) {
                uint32_t b0 = __float_as_uint(s_w[(kk * 8 + tq) * W_STRIDE + bcol]);
                uint32_t b1r = __float_as_uint(s_w[(kk * 8 + tq + 4) * W_STRIDE + bcol]);
                mma_tf32(acc[nt], A[kk], b0, b1r);
            }
        }
    }

    // ---- epilogue: bias + relu + classifier, straight from fragments ----
    // Thread holds rows {w*16+g, w*16+g+8}, cols {nt*8 + 2*tq, +1}.
    float part[2][16];
    #pragma unroll
    for (int rr = 0; rr < 2; rr++)
        #pragma unroll
        for (int j = 0; j < 16; j++) part[rr][j] = 0.f;

    #pragma unroll
    for (int nt = 0; nt < 16; nt++) {
        int c0 = nt * 8 + 2 * tq;
        float h00 = fmaxf(acc[nt][0] + s_bl[c0],     0.f);
        float h01 = fmaxf(acc[nt][1] + s_bl[c0 + 1], 0.f);
        float h10 = fmaxf(acc[nt][2] + s_bl[c0],     0.f);
        float h11 = fmaxf(acc[nt][3] + s_bl[c0 + 1], 0.f);
        #pragma unroll
        for (int j = 0; j < 16; j++) {
            float w0 = s_w1t[j * 128 + c0];
            float w1 = s_w1t[j * 128 + c0 + 1];
            part[0][j] += h00 * w0 + h01 * w1;
            part[1][j] += h10 * w0 + h11 * w1;
        }
    }
    #pragma unroll
    for (int rr = 0; rr < 2; rr++)
        #pragma unroll
        for (int j = 0; j < 16; j++) {
            part[rr][j] += __shfl_xor_sync(0xffffffffu, part[rr][j], 1);
            part[rr][j] += __shfl_xor_sync(0xffffffffu, part[rr][j], 2);
        }

    if (tq == 0) {
        #pragma unroll
        for (int rr = 0; rr < 2; rr++) {
            int node = m0 + w * 16 + g + rr * 8;
            if (node < N) {
                float o0 = b2[0], o1 = b2[1];
                #pragma unroll
                for (int j = 0; j < 16; j++) {
                    float tv = fmaxf(part[rr][j] + b1[j], 0.f);
                    o0 += tv * W2[j * 2 + 0];
                    o1 += tv * W2[j * 2 + 1];
                }
                out[(size_t)node * 2 + 0] = o0;
                out[(size_t)node * 2 + 1] = o1;
            }
        }
    }
}

// ---------------- launcher --------------------------------------------
extern "C" void kernel_launch(void* const* d_in, const int* in_sizes, int n_in,
                              void* d_out, int out_size) {
    const float* x  = (const float*)d_in[0];
    const int*   ei = (const int*)d_in[1];     // int64 ref -> int32 in harness
    int N = in_sizes[0] / D;
    int E = in_sizes[1] / 2;

    const int want[9] = {64, 64, 8192, 128, 8192, 2048, 16, 32, 2};
    const float* wptr[9] = {nullptr, nullptr, nullptr, nullptr, nullptr,
                            nullptr, nullptr, nullptr, nullptr};
    int j = 0;
    for (int i = 2; i < n_in && j < 9; i++) {
        if (in_sizes[i] == want[j]) { wptr[j] = (const float*)d_in[i]; j++; }
    }
    const float *gamma = wptr[0], *beta = wptr[1], *Wl = wptr[2], *bl = wptr[3],
                *Wr = wptr[4], *W1 = wptr[5], *b1 = wptr[6], *W2 = wptr[7],
                *b2 = wptr[8];
    float* out = (float*)d_out;

    k_zero<<<1024, 256>>>(N);
    k_stats<<<(N + 1023) / 1024, 256>>>(x, N);
    k_norm<<<2048, 256>>>(x, gamma, beta, N);
    long long total = (long long)E * 16;
    k_scatter<<<(int)((total + 255) / 256), 256>>>(ei, E, N);
    k_fused_tc<<<(N + 127) / 128, 256>>>(Wl, bl, Wr, W1, b1, W2, b2, out, N);
}

// round 6
// speedup vs baseline: 1.7769x; 1.1805x over previous
#include <cuda_runtime.h>
#include <cstdint>

// ---------------- problem constants (fixed by dataset) ----------------
#define NMAX 100000
#define D    64
#define H    128
#define DV   (D / 4)   // 16 float4 per row

// ---------------- device scratch (static allocation, allowed) ---------
// Invariant: every kernel leaves its scratch zeroed for the next replay.
__device__ float4 g_agg4[ (size_t)NMAX * DV ];   // segment sums (zeroed by k_fused_tc)
__device__ float  g_deg [ NMAX ];                // degree       (zeroed by k_fused_tc)
__device__ float  g_stats[ 2 * D ];              // colsum/colsumsq (zeroed by k_stats finalize)
__device__ float4 g_sc4[ DV ];                   // BN scale per column (packed)
__device__ float4 g_sb4[ DV ];                   // BN bias  per column (packed)
__device__ unsigned g_ticket;                    // k_stats completion ticket

// ---------------- helpers ---------------------------------------------
__device__ __forceinline__ float f2tf32f(float x) {
    uint32_t r;
    asm("cvt.rna.tf32.f32 %0, %1;" : "=r"(r) : "f"(x));
    return __uint_as_float(r);
}

__device__ __forceinline__ void mma_tf32(float* c, const uint32_t* a,
                                         uint32_t b0, uint32_t b1) {
    asm("mma.sync.aligned.m16n8k8.row.col.f32.tf32.tf32.f32 "
        "{%0,%1,%2,%3}, {%4,%5,%6,%7}, {%8,%9}, {%0,%1,%2,%3};"
        : "+f"(c[0]), "+f"(c[1]), "+f"(c[2]), "+f"(c[3])
        : "r"(a[0]), "r"(a[1]), "r"(a[2]), "r"(a[3]), "r"(b0), "r"(b1));
}

// ---------------- kernel 1: BN stats + fused finalize -----------------
// block = 256 threads, 1024 rows each. Last finished block computes
// sc/sb, then re-zeros g_stats and the ticket (replay invariant).
__global__ void k_stats(const float* __restrict__ x,
                        const float* __restrict__ gamma,
                        const float* __restrict__ beta, int N) {
    __shared__ float s_sum[4][D];
    __shared__ float s_sq [4][D];
    __shared__ bool  s_last;
    int c  = threadIdx.x & (D - 1);
    int rg = threadIdx.x >> 6;
    int row0 = blockIdx.x * 1024;
    int rend = min(row0 + 1024, N);
    float s = 0.f, q = 0.f;
    for (int r = row0 + rg; r < rend; r += 4) {
        float v = x[(size_t)r * D + c];
        s += v; q += v * v;
    }
    s_sum[rg][c] = s; s_sq[rg][c] = q;
    __syncthreads();
    if (threadIdx.x < D) {
        float S = s_sum[0][c] + s_sum[1][c] + s_sum[2][c] + s_sum[3][c];
        float Q = s_sq [0][c] + s_sq [1][c] + s_sq [2][c] + s_sq [3][c];
        atomicAdd(&g_stats[c], S);
        atomicAdd(&g_stats[D + c], Q);
    }
    __threadfence();
    if (threadIdx.x == 0)
        s_last = (atomicAdd(&g_ticket, 1u) == (unsigned)gridDim.x - 1u);
    __syncthreads();
    if (s_last && threadIdx.x < D) {
        float invN = 1.0f / (float)N;
        float mean = g_stats[c] * invN;
        float var  = g_stats[D + c] * invN - mean * mean;
        float inv  = rsqrtf(var + 1e-5f);
        float g    = gamma[c];
        reinterpret_cast<float*>(g_sc4)[c] = inv * g;
        reinterpret_cast<float*>(g_sb4)[c] = beta[c] - mean * inv * g;
        g_stats[c] = 0.f; g_stats[D + c] = 0.f;        // reset for next replay
        if (threadIdx.x == 0) g_ticket = 0u;
        __threadfence();
    }
}

// ---------------- kernel 2: edge scatter w/ on-the-fly normalize ------
// 16 threads per edge, one float4 vector reduction-atomic per thread.
__global__ void k_scatter(const int* __restrict__ ei,
                          const float4* __restrict__ x4, int E, int N) {
    long long idx = (long long)blockIdx.x * blockDim.x + threadIdx.x;
    int e = (int)(idx >> 4);
    if (e >= E) return;
    int lane = (int)(idx & 15);
    int src = ei[e];
    int dst = ei[(size_t)E + e];
    if ((unsigned)src >= (unsigned)N || (unsigned)dst >= (unsigned)N) return;
    float4 v  = x4[(size_t)src * DV + lane];
    float4 sc = g_sc4[lane];
    float4 sb = g_sb4[lane];
    v.x = fmaf(v.x, sc.x, sb.x);
    v.y = fmaf(v.y, sc.y, sb.y);
    v.z = fmaf(v.z, sc.z, sb.z);
    v.w = fmaf(v.w, sc.w, sb.w);
    atomicAdd(&g_agg4[(size_t)dst * DV + lane], v);
    if (lane == 0) atomicAdd(&g_deg[dst], 1.0f);
}

// ---------------- kernel 3: tf32 tensor-core GEMM + fused classifier --
// h = relu([agg/deg, xn] @ [W_l; W_r] + b_l), xn computed on the fly.
// out = relu(h @ W1 + b1) @ W2 + b2, straight from mma fragments.
// Also re-zeros its g_agg4/g_deg tile after last read (replay invariant).
#define U_STRIDE 36
#define W_STRIDE 132
__global__ void __launch_bounds__(256)
k_fused_tc(const float4* __restrict__ x4,
           const float* __restrict__ Wl, const float* __restrict__ bl,
           const float* __restrict__ Wr, const float* __restrict__ W1,
           const float* __restrict__ b1, const float* __restrict__ W2,
           const float* __restrict__ b2, float* __restrict__ out, int N) {
    __shared__ float s_u [128 * U_STRIDE];   // U chunk  [128 rows][32 k], tf32
    __shared__ float s_w [32 * W_STRIDE];    // W chunk  [32 k][128 h], tf32
    __shared__ float s_w1t[16 * 128];        // W1^T [j][h]
    __shared__ float s_bl[128];
    __shared__ float4 s_sc[DV], s_sb[DV];

    int t    = threadIdx.x;
    int w    = t >> 5;
    int lane = t & 31;
    int g    = lane >> 2;     // group id 0..7
    int tq   = lane & 3;      // thread-in-quad 0..3
    int m0   = blockIdx.x * 128;

    if (t < 128) s_bl[t] = bl[t];
    if (t < DV)      s_sc[t] = g_sc4[t];
    else if (t < 2 * DV) s_sb[t - DV] = g_sb4[t - DV];
    for (int i = t; i < 16 * 128; i += 256) {      // W1 [128][16] -> W1T[j][h]
        int c = i & 127, j = i >> 7;
        s_w1t[j * 128 + c] = W1[c * 16 + j];
    }

    float acc[16][4];
    #pragma unroll
    for (int n = 0; n < 16; n++)
        #pragma unroll
        for (int j = 0; j < 4; j++) acc[n][j] = 0.f;

    #pragma unroll
    for (int kb = 0; kb < 4; kb++) {
        __syncthreads();
        // ---- load U chunk: 128 rows x 32 k (tf32) ----
        #pragma unroll
        for (int ii = 0; ii < 4; ii++) {
            int i = t + 256 * ii;            // 0..1023 float4 units
            int row = i >> 3, k4 = i & 7;
            int node = m0 + row;
            int kg = kb * 32 + k4 * 4;
            float4 v = make_float4(0.f, 0.f, 0.f, 0.f);
            if (node < N) {
                if (kg < D) {
                    v = g_agg4[(size_t)node * DV + (kg >> 2)];
                    float inv = 1.0f / fmaxf(g_deg[node], 1.0f);
                    v.x *= inv; v.y *= inv; v.z *= inv; v.w *= inv;
                } else {
                    int kx = (kg - D) >> 2;
                    v = x4[(size_t)node * DV + kx];
                    float4 sc = s_sc[kx], sb = s_sb[kx];
                    v.x = fmaf(v.x, sc.x, sb.x);
                    v.y = fmaf(v.y, sc.y, sb.y);
                    v.z = fmaf(v.z, sc.z, sb.z);
                    v.w = fmaf(v.w, sc.w, sb.w);
                }
            }
            float* p = &s_u[row * U_STRIDE + k4 * 4];
            p[0] = f2tf32f(v.x); p[1] = f2tf32f(v.y);
            p[2] = f2tf32f(v.z); p[3] = f2tf32f(v.w);
        }
        // ---- load W chunk: 32 k x 128 h (tf32) ----
        #pragma unroll
        for (int ii = 0; ii < 4; ii++) {
            int i = t + 256 * ii;            // 0..1023 float4 units
            int k = i >> 5, h4 = i & 31;
            int kg = kb * 32 + k;
            const float* src = (kg < D) ? (Wl + (size_t)kg * H + h4 * 4)
                                        : (Wr + (size_t)(kg - D) * H + h4 * 4);
            float4 v = *reinterpret_cast<const float4*>(src);
            float* p = &s_w[k * W_STRIDE + h4 * 4];
            p[0] = f2tf32f(v.x); p[1] = f2tf32f(v.y);
            p[2] = f2tf32f(v.z); p[3] = f2tf32f(v.w);
        }
        __syncthreads();

        // ---- A fragments for this chunk (4 k-steps of 8) ----
        uint32_t A[4][4];
        int arow = (w * 16 + g) * U_STRIDE;
        #pragma unroll
        for (int kk = 0; kk < 4; kk++) {
            int kof = kk * 8 + tq;
            A[kk][0] = __float_as_uint(s_u[arow + kof]);
            A[kk][1] = __float_as_uint(s_u[arow + 8 * U_STRIDE + kof]);
            A[kk][2] = __float_as_uint(s_u[arow + kof + 4]);
            A[kk][3] = __float_as_uint(s_u[arow + 8 * U_STRIDE + kof + 4]);
        }
        // ---- 16 n-tiles x 4 k-steps of mma ----
        #pragma unroll
        for (int nt = 0; nt < 16; nt++) {
            int bcol = nt * 8 + g;
            #pragma unroll
            for (int kk = 0; kk < 4; kk++) {
                uint32_t b0 = __float_as_uint(s_w[(kk * 8 + tq) * W_STRIDE + bcol]);
                uint32_t b1r = __float_as_uint(s_w[(kk * 8 + tq + 4) * W_STRIDE + bcol]);
                mma_tf32(acc[nt], A[kk], b0, b1r);
            }
        }
    }

    // ---- re-zero this block's agg/deg tile (after last read) ----
    __syncthreads();
    {
        float4 z = make_float4(0.f, 0.f, 0.f, 0.f);
        #pragma unroll
        for (int ii = 0; ii < 8; ii++) {
            int i = t + 256 * ii;            // 0..2047 float4 units
            int row = i >> 4;
            int node = m0 + row;
            if (node < N) g_agg4[(size_t)node * DV + (i & 15)] = z;
        }
        if (t < 128 && m0 + t < N) g_deg[m0 + t] = 0.f;
    }

    // ---- epilogue: bias + relu + classifier, straight from fragments ----
    float part[2][16];
    #pragma unroll
    for (int rr = 0; rr < 2; rr++)
        #pragma unroll
        for (int j = 0; j < 16; j++) part[rr][j] = 0.f;

    #pragma unroll
    for (int nt = 0; nt < 16; nt++) {
        int c0 = nt * 8 + 2 * tq;
        float h00 = fmaxf(acc[nt][0] + s_bl[c0],     0.f);
        float h01 = fmaxf(acc[nt][1] + s_bl[c0 + 1], 0.f);
        float h10 = fmaxf(acc[nt][2] + s_bl[c0],     0.f);
        float h11 = fmaxf(acc[nt][3] + s_bl[c0 + 1], 0.f);
        #pragma unroll
        for (int j = 0; j < 16; j++) {
            float w0 = s_w1t[j * 128 + c0];
            float w1 = s_w1t[j * 128 + c0 + 1];
            part[0][j] += h00 * w0 + h01 * w1;
            part[1][j] += h10 * w0 + h11 * w1;
        }
    }
    #pragma unroll
    for (int rr = 0; rr < 2; rr++)
        #pragma unroll
        for (int j = 0; j < 16; j++) {
            part[rr][j] += __shfl_xor_sync(0xffffffffu, part[rr][j], 1);
            part[rr][j] += __shfl_xor_sync(0xffffffffu, part[rr][j], 2);
        }

    if (tq == 0) {
        #pragma unroll
        for (int rr = 0; rr < 2; rr++) {
            int node = m0 + w * 16 + g + rr * 8;
            if (node < N) {
                float o0 = b2[0], o1 = b2[1];
                #pragma unroll
                for (int j = 0; j < 16; j++) {
                    float tv = fmaxf(part[rr][j] + b1[j], 0.f);
                    o0 += tv * W2[j * 2 + 0];
                    o1 += tv * W2[j * 2 + 1];
                }
                out[(size_t)node * 2 + 0] = o0;
                out[(size_t)node * 2 + 1] = o1;
            }
        }
    }
}

// ---------------- launcher --------------------------------------------
extern "C" void kernel_launch(void* const* d_in, const int* in_sizes, int n_in,
                              void* d_out, int out_size) {
    const float*  x  = (const float*)d_in[0];
    const float4* x4 = (const float4*)d_in[0];
    const int*    ei = (const int*)d_in[1];   // int64 ref -> int32 in harness
    int N = in_sizes[0] / D;
    int E = in_sizes[1] / 2;

    const int want[9] = {64, 64, 8192, 128, 8192, 2048, 16, 32, 2};
    const float* wptr[9] = {nullptr, nullptr, nullptr, nullptr, nullptr,
                            nullptr, nullptr, nullptr, nullptr};
    int j = 0;
    for (int i = 2; i < n_in && j < 9; i++) {
        if (in_sizes[i] == want[j]) { wptr[j] = (const float*)d_in[i]; j++; }
    }
    const float *gamma = wptr[0], *beta = wptr[1], *Wl = wptr[2], *bl = wptr[3],
                *Wr = wptr[4], *W1 = wptr[5], *b1 = wptr[6], *W2 = wptr[7],
                *b2 = wptr[8];
    float* out = (float*)d_out;

    k_stats<<<(N + 1023) / 1024, 256>>>(x, gamma, beta, N);
    long long total = (long long)E * 16;
    k_scatter<<<(int)((total + 255) / 256), 256>>>(ei, x4, E, N);
    k_fused_tc<<<(N + 127) / 128, 256>>>(x4, Wl, bl, Wr, W1, b1, W2, b2, out, N);
}